// round 4
// baseline (speedup 1.0000x reference)
#include <cuda_runtime.h>

// R4: row-tiled (5 rows/CTA, input chunk held in registers -> 5x less L2
// input traffic), fused last-block final reduction (kills the 5.6us second
// kernel), 16KB chunks for smoother wave structure.

#define D_ELEMS   1048576
#define N_ROWS    50
#define RPG       5                      /* rows per group/CTA */
#define NGROUPS   (N_ROWS / RPG)         /* 10 */
#define TPB       256
#define CHUNK     4096                   /* elems per chunk = 16 KB */
#define NCHUNK    (D_ELEMS / CHUNK)      /* 256 */
#define NBLOCKS   (NCHUNK * NGROUPS)     /* 2560 */
/* per thread: CHUNK/TPB = 16 elems = 4 float4 */

__device__ float        g_part[N_ROWS * NCHUNK];
__device__ unsigned int g_arrival;       /* zero-init; self-resets each run */

__global__ __launch_bounds__(TPB) void matvec_fused(
    const float* __restrict__ inp,
    const float* __restrict__ fc,
    float* __restrict__ out)
{
    const int chunk = blockIdx.x;        /* 0..NCHUNK-1 */
    const int grp   = blockIdx.y;        /* 0..NGROUPS-1 */
    const int t     = threadIdx.x;
    const int wid   = t >> 5;
    const int lid   = t & 31;
    const size_t base = (size_t)chunk * CHUNK;

    /* input chunk: 4 float4 per thread, held in registers, reused x5 rows */
    const float4* __restrict__ v = reinterpret_cast<const float4*>(inp + base);
    float4 a0 = v[t];
    float4 a1 = v[t +     TPB];
    float4 a2 = v[t + 2 * TPB];
    float4 a3 = v[t + 3 * TPB];

    float acc[RPG];
    #pragma unroll
    for (int r = 0; r < RPG; r++) {
        const float4* __restrict__ m = reinterpret_cast<const float4*>(
            fc + (size_t)(grp * RPG + r) * D_ELEMS + base);
        float4 b0 = m[t];
        float4 b1 = m[t +     TPB];
        float4 b2 = m[t + 2 * TPB];
        float4 b3 = m[t + 3 * TPB];
        float s = 0.f;
        s = fmaf(a0.x, b0.x, s); s = fmaf(a0.y, b0.y, s);
        s = fmaf(a0.z, b0.z, s); s = fmaf(a0.w, b0.w, s);
        s = fmaf(a1.x, b1.x, s); s = fmaf(a1.y, b1.y, s);
        s = fmaf(a1.z, b1.z, s); s = fmaf(a1.w, b1.w, s);
        s = fmaf(a2.x, b2.x, s); s = fmaf(a2.y, b2.y, s);
        s = fmaf(a2.z, b2.z, s); s = fmaf(a2.w, b2.w, s);
        s = fmaf(a3.x, b3.x, s); s = fmaf(a3.y, b3.y, s);
        s = fmaf(a3.z, b3.z, s); s = fmaf(a3.w, b3.w, s);
        acc[r] = s;
    }

    /* block-reduce each of the 5 row accumulators */
    __shared__ float s_part[RPG][TPB / 32];
    #pragma unroll
    for (int r = 0; r < RPG; r++) {
        float x = acc[r];
        #pragma unroll
        for (int o = 16; o > 0; o >>= 1)
            x += __shfl_down_sync(0xffffffffu, x, o);
        if (lid == 0) s_part[r][wid] = x;
    }
    __syncthreads();
    if (wid < RPG && lid < TPB / 32) {
        float x = s_part[wid][lid];
        #pragma unroll
        for (int o = (TPB / 64); o > 0; o >>= 1)
            x += __shfl_down_sync((1u << (TPB / 32)) - 1u, x, o);
        if (lid == 0)
            g_part[(grp * RPG + wid) * NCHUNK + chunk] = x;
    }

    /* last-arriving CTA does the final reduction (deterministic fixed order) */
    __shared__ int s_last;
    __syncthreads();
    if (t == 0) {
        __threadfence();  /* publish g_part writes before arrival */
        unsigned int c = atomicAdd(&g_arrival, 1u);
        s_last = (c == NBLOCKS - 1);
    }
    __syncthreads();
    if (s_last) {
        __threadfence();  /* acquire: see all other CTAs' g_part writes */
        /* 8 warps over 50 rows; each warp sums 256 partials for its row */
        for (int row = wid; row < N_ROWS; row += TPB / 32) {
            float s = 0.f;
            #pragma unroll 4
            for (int i = lid; i < NCHUNK; i += 32)
                s += g_part[row * NCHUNK + i];
            #pragma unroll
            for (int o = 16; o > 0; o >>= 1)
                s += __shfl_down_sync(0xffffffffu, s, o);
            if (lid == 0) out[row] = s;
        }
        if (t == 0) g_arrival = 0;  /* reset for next graph replay */
    }
}

extern "C" void kernel_launch(void* const* d_in, const int* in_sizes, int n_in,
                              void* d_out, int out_size)
{
    const float* inp = (const float*)d_in[0];   // [D]
    const float* fc  = (const float*)d_in[1];   // [N_ROWS, D]
    float* out = (float*)d_out;                 // [N_ROWS]

    dim3 grid(NCHUNK, NGROUPS);
    matvec_fused<<<grid, TPB>>>(inp, fc, out);
}